// round 1
// baseline (speedup 1.0000x reference)
#include <cuda_runtime.h>
#include <math.h>

#define NTOK 16384
#define HD 768
#define FF 3072
#define NE 4

// Scratch as device globals (no allocations allowed in kernel_launch).
__device__ int   g_counts[NE];
__device__ int   g_idx[NE * NTOK];
__device__ float g_H[(size_t)NTOK * FF];   // GELU(x@W1+b1), token-indexed rows
__device__ float g_Y[(size_t)NTOK * HD];   // h@W2+b2, token-indexed rows

__global__ void k_zero() {
    if (threadIdx.x < NE) g_counts[threadIdx.x] = 0;
}

__global__ void k_build(const int* __restrict__ ts) {
    int t = blockIdx.x * blockDim.x + threadIdx.x;
    if (t < NTOK) {
        int e = ts[t];
        if (e > 0) {
            int s = atomicAdd(&g_counts[e - 1], 1);
            g_idx[(e - 1) * NTOK + s] = t;
        }
    }
}

// Gathered SGEMM: O[tok, col0:col0+64] = A[tok, :] @ W[e] (+bias, opt GELU)
// Tile: BM=128, BN=64, BK=16, 256 threads, 8x4 per-thread register tile.
template<int KT, int NT, bool FIRST>
__global__ void __launch_bounds__(256) k_gemm(const float* __restrict__ X,
                                              const float* __restrict__ W,
                                              const float* __restrict__ bias) {
    const float* A = FIRST ? X : g_H;
    float* O = FIRST ? g_H : g_Y;

    const int e = blockIdx.z;
    const int cnt = g_counts[e];
    const int row0 = blockIdx.y * 128;
    if (row0 >= cnt) return;
    const int col0 = blockIdx.x * 64;

    __shared__ int   toks[128];
    __shared__ float As[16][128];
    __shared__ float Bs[16][64];

    const int t = threadIdx.x;
    if (t < 128) {
        int r = row0 + t;
        toks[t] = (r < cnt) ? g_idx[e * NTOK + r] : -1;
    }
    __syncthreads();

    const int tx = t & 15;         // 16 col-groups of 4
    const int ty = t >> 4;         // 16 row-groups of 8

    float acc[8][4];
    #pragma unroll
    for (int i = 0; i < 8; i++)
        #pragma unroll
        for (int j = 0; j < 4; j++) acc[i][j] = 0.f;

    const int ar = t >> 2;          // 0..63 (row within half-tile)
    const int ak = (t & 3) * 4;     // k offset 0,4,8,12
    const int bk = t >> 4;          // 0..15
    const int bn = (t & 15) * 4;    // 0..60

    for (int k0 = 0; k0 < KT; k0 += 16) {
        #pragma unroll
        for (int h = 0; h < 2; h++) {
            int r = ar + h * 64;
            int tok = toks[r];
            float4 v = make_float4(0.f, 0.f, 0.f, 0.f);
            if (tok >= 0)
                v = *(const float4*)&A[(size_t)tok * KT + k0 + ak];
            As[ak + 0][r] = v.x;
            As[ak + 1][r] = v.y;
            As[ak + 2][r] = v.z;
            As[ak + 3][r] = v.w;
        }
        {
            float4 v = *(const float4*)&W[((size_t)e * KT + k0 + bk) * NT + col0 + bn];
            *(float4*)&Bs[bk][bn] = v;
        }
        __syncthreads();

        #pragma unroll
        for (int k = 0; k < 16; k++) {
            float a[8], b[4];
            *(float4*)&a[0] = *(const float4*)&As[k][ty * 8];
            *(float4*)&a[4] = *(const float4*)&As[k][ty * 8 + 4];
            *(float4*)&b[0] = *(const float4*)&Bs[k][tx * 4];
            #pragma unroll
            for (int i = 0; i < 8; i++)
                #pragma unroll
                for (int j = 0; j < 4; j++)
                    acc[i][j] = fmaf(a[i], b[j], acc[i][j]);
        }
        __syncthreads();
    }

    #pragma unroll
    for (int i = 0; i < 8; i++) {
        int r = ty * 8 + i;
        int tok = toks[r];
        if (tok < 0) continue;
        float4 v;
        float* vv = (float*)&v;
        #pragma unroll
        for (int j = 0; j < 4; j++) {
            float u = acc[i][j] + bias[e * NT + col0 + tx * 4 + j];
            if (FIRST) u = 0.5f * u * (1.f + erff(u * 0.70710678118654752f));
            vv[j] = u;
        }
        *(float4*)&O[(size_t)tok * NT + col0 + tx * 4] = v;
    }
}

__device__ __forceinline__ float2 blk_sum(float a, float b, float2* red) {
    int lane = threadIdx.x & 31;
    int w = threadIdx.x >> 5;
    #pragma unroll
    for (int o = 16; o > 0; o >>= 1) {
        a += __shfl_xor_sync(0xffffffffu, a, o);
        b += __shfl_xor_sync(0xffffffffu, b, o);
    }
    if (lane == 0) red[w] = make_float2(a, b);
    __syncthreads();
    if (w == 0) {
        float2 v = (lane < 8) ? red[lane] : make_float2(0.f, 0.f);
        a = v.x; b = v.y;
        #pragma unroll
        for (int o = 4; o > 0; o >>= 1) {
            a += __shfl_xor_sync(0xffffffffu, a, o);
            b += __shfl_xor_sync(0xffffffffu, b, o);
        }
        if (lane == 0) red[0] = make_float2(a, b);
    }
    __syncthreads();
    float2 res = red[0];
    __syncthreads();
    return res;
}

// One block per token: inner residual-LN (per expert) + select + outer residual-LN.
__global__ void __launch_bounds__(256) k_ln(const float* __restrict__ x,
                                            const int* __restrict__ ts,
                                            const float* __restrict__ ln_g,
                                            const float* __restrict__ ln_b,
                                            const float* __restrict__ og,
                                            const float* __restrict__ ob,
                                            float* __restrict__ out) {
    __shared__ float2 red[8];
    const int t = blockIdx.x;
    const int tid = threadIdx.x;
    const int e = ts[t];   // uniform per block

    float xv[3], sv[3];
    #pragma unroll
    for (int k = 0; k < 3; k++) xv[k] = x[(size_t)t * HD + tid + 256 * k];

    if (e > 0) {
        float yv[3];
        float s = 0.f, s2 = 0.f;
        #pragma unroll
        for (int k = 0; k < 3; k++) {
            yv[k] = g_Y[(size_t)t * HD + tid + 256 * k] + xv[k];
            s += yv[k];
            s2 += yv[k] * yv[k];
        }
        float2 r = blk_sum(s, s2, red);
        float m = r.x * (1.f / (float)HD);
        float var = r.y * (1.f / (float)HD) - m * m;
        float inv = rsqrtf(fmaxf(var, 0.f) + 1e-12f);
        #pragma unroll
        for (int k = 0; k < 3; k++) {
            int c = tid + 256 * k;
            sv[k] = (yv[k] - m) * inv * ln_g[(e - 1) * HD + c] + ln_b[(e - 1) * HD + c];
        }
    } else {
        sv[0] = sv[1] = sv[2] = 0.f;
    }

    float zv[3];
    float s = 0.f, s2 = 0.f;
    #pragma unroll
    for (int k = 0; k < 3; k++) {
        zv[k] = sv[k] + xv[k];
        s += zv[k];
        s2 += zv[k] * zv[k];
    }
    float2 r = blk_sum(s, s2, red);
    float m = r.x * (1.f / (float)HD);
    float var = r.y * (1.f / (float)HD) - m * m;
    float inv = rsqrtf(fmaxf(var, 0.f) + 1e-12f);
    #pragma unroll
    for (int k = 0; k < 3; k++) {
        int c = tid + 256 * k;
        out[(size_t)t * HD + c] = (zv[k] - m) * inv * og[c] + ob[c];
    }
}

extern "C" void kernel_launch(void* const* d_in, const int* in_sizes, int n_in,
                              void* d_out, int out_size) {
    const float* x    = (const float*)d_in[0];   // [8,2048,768]
    const int*   ts   = (const int*)  d_in[1];   // [8,2048]
    const float* W1   = (const float*)d_in[2];   // [4,768,3072]
    const float* b1   = (const float*)d_in[3];   // [4,3072]
    const float* W2   = (const float*)d_in[4];   // [4,3072,768]
    const float* b2   = (const float*)d_in[5];   // [4,768]
    const float* ln_g = (const float*)d_in[6];   // [4,768]
    const float* ln_b = (const float*)d_in[7];   // [4,768]
    const float* og   = (const float*)d_in[8];   // [768]
    const float* ob   = (const float*)d_in[9];   // [768]
    float* out = (float*)d_out;

    k_zero<<<1, 32>>>();
    k_build<<<(NTOK + 255) / 256, 256>>>(ts);

    dim3 g1(FF / 64, NTOK / 128, NE);
    k_gemm<HD, FF, true><<<g1, 256>>>(x, W1, b1);

    dim3 g2(HD / 64, NTOK / 128, NE);
    k_gemm<FF, HD, false><<<g2, 256>>>(x, W2, b2);

    k_ln<<<NTOK, 256>>>(x, ts, ln_g, ln_b, og, ob, out);
}